// round 16
// baseline (speedup 1.0000x reference)
#include <cuda_runtime.h>

#define BB   8
#define QQ   256
#define KK   1024
#define DD   256
#define HH   128
#define DVV  128
#define LOG2E 1.44269504088896340736f

typedef unsigned long long u64;

// Scratch (allocation-free: device globals)
// Ek4 layout (R13 original interleave): float4 granule = 4 h values for ONE k:
//   index = ((b*(HH/4) + hq)*KK + k) * 4 + h%4
__device__ float g_Eq [BB * QQ * HH];        // [b][q][h]   = exp(2*qproj)
__device__ float g_Ek4[BB * (HH/4) * KK * 4];

__device__ __forceinline__ float frcp(float x) {
    float r; asm("rcp.approx.f32 %0, %1;" : "=f"(r) : "f"(x)); return r;
}
__device__ __forceinline__ float fex2(float x) {
    float r; asm("ex2.approx.f32 %0, %1;" : "=f"(r) : "f"(x)); return r;
}
// ---- f32x2 packed helpers (FFMA2: PTX-only, full-rate, IEEE per lane) ----
__device__ __forceinline__ u64 ffma2(u64 a, u64 b, u64 c) {
    u64 d; asm("fma.rn.f32x2 %0, %1, %2, %3;" : "=l"(d) : "l"(a), "l"(b), "l"(c));
    return d;
}
__device__ __forceinline__ u64 fmul2(u64 a, u64 b) {
    u64 d; asm("mul.rn.f32x2 %0, %1, %2;" : "=l"(d) : "l"(a), "l"(b));
    return d;
}
__device__ __forceinline__ u64 dup2(float x) {
    u64 d; asm("mov.b64 %0, {%1, %1};" : "=l"(d) : "f"(x));
    return d;
}
__device__ __forceinline__ float2 unpk(u64 a) {
    float2 f; asm("mov.b64 {%0, %1}, %2;" : "=f"(f.x), "=f"(f.y) : "l"(a));
    return f;
}
__device__ __forceinline__ u64 pk(float x, float y) {
    u64 d; asm("mov.b64 %0, {%1, %2};" : "=l"(d) : "f"(x), "f"(y));
    return d;
}

// ---------------------------------------------------------------------------
// Kernel 1: merged projection + exp. 32 rows per block, 512 threads:
// tid&127 = output column h, tid>>7 = row-half (8 rows each). All 4 halves
// issue the same W addresses -> one L1 fill serves the block; W L2 traffic
// halves vs PR=16. W native [d][h] (coalesced), depth-1 prefetch, f32x2.
//   blocks [0,64)   : query rows -> g_Eq[row][h]
//   blocks [64,320) : key rows   -> g_Ek4 (R13 interleave)
// ---------------------------------------------------------------------------
#define PR 32
__global__ __launch_bounds__(512)
void proj_kernel(const float* __restrict__ Q, const float* __restrict__ Kx,
                 const float* __restrict__ Wq, const float* __restrict__ Wk) {
    __shared__ __align__(16) float xs[PR][DD];     // 32 input rows (32 KB)
    __shared__ float es[HH][PR + 1];               // padded transpose buffer
    int blk  = blockIdx.x;
    bool isK = blk >= (BB * QQ) / PR;              // >= 64
    int rowbase = isK ? (blk - (BB * QQ) / PR) * PR : blk * PR;
    const float* X = isK ? Kx : Q;
    const float* W = isK ? Wk : Wq;
    int tid  = threadIdx.x;
    int h    = tid & 127;                          // output column
    int half = tid >> 7;                           // row-half: 0..3
    int r0   = half * 8;                           // first of 8 rows

    {   // coalesced float4 row load (512 threads)
        const float4* Xp = (const float4*)(X + (size_t)rowbase * DD);
        float4* xsp = (float4*)xs;
        for (int i = tid; i < PR * DD / 4; i += 512) xsp[i] = Xp[i];
    }
    __syncthreads();

    u64 acc2[8];
#pragma unroll
    for (int r = 0; r < 8; r++) acc2[r] = 0ull;

    const float* Wp = W + h;
    float w0 = Wp[0 * HH], w1 = Wp[1 * HH], w2 = Wp[2 * HH], w3 = Wp[3 * HH];
    for (int d4 = 0; d4 < DD / 4; d4++) {
        u64 cp01 = pk(w0, w1), cp23 = pk(w2, w3);
        if (d4 + 1 < DD / 4) {                     // prefetch next W quad
            const float* Wn = Wp + (d4 + 1) * 4 * HH;
            w0 = Wn[0 * HH]; w1 = Wn[1 * HH]; w2 = Wn[2 * HH]; w3 = Wn[3 * HH];
        }
        int d = d4 * 4;
#pragma unroll
        for (int r = 0; r < 8; r++) {
            ulonglong2 x2 = *(const ulonglong2*)&xs[r0 + r][d]; // LDS.128
            acc2[r] = ffma2(x2.x, cp01, acc2[r]);
            acc2[r] = ffma2(x2.y, cp23, acc2[r]);
        }
    }

    if (!isK) {
#pragma unroll
        for (int r = 0; r < 8; r++) {
            float2 f = unpk(acc2[r]);
            g_Eq[(rowbase + r0 + r) * HH + h] =
                fex2((f.x + f.y) * (2.0f * LOG2E));
        }
    } else {
#pragma unroll
        for (int r = 0; r < 8; r++) {
            float2 f = unpk(acc2[r]);
            es[h][r0 + r] = fex2((f.x + f.y) * (2.0f * LOG2E));
        }
        __syncthreads();
        int b  = rowbase >> 10;
        int k0 = rowbase & 1023;
        // R13 interleave: [hq][k][h%4], consecutive i -> consecutive addr
        for (int i = tid; i < HH * PR; i += 512) {
            int hq = i >> 7;              // 128 = PR*4 elements per h-quad
            int r  = (i >> 2) & (PR - 1);
            int h2 = i & 3;
            g_Ek4[(((size_t)b * (HH/4) + hq) * KK + k0 + r) * 4 + h2]
                = es[hq * 4 + h2][r];
        }
    }
}

// ---------------------------------------------------------------------------
// Kernel 2: fused scores + exp + softmax-denominator + attn@V.
// Block = (b, tile of 4 q-rows), 512 blocks (ONE resident wave), 256 thr.
//   s = sum_h (-2 w_h) * rcp(1 + Eq*Ek)   (wsum cancels in softmax)
// LOAD ADDRESSES BYTE-IDENTICAL to the frozen R5 structure (R13 granule).
// f32x2 lanes = q-pairs (q0,q1)/(q2,q3): eq needs NO dup (one LDS.128 per h
// feeds all 4 q); ek dup2 8/iter; w dups shared across q-pairs. L1
// wavefronts/element -44% vs q=2 k-pack. Quad-h rcp: 4 MUFU per (k,qpair).
// __launch_bounds__(256,4): 4 blocks/SM (smem 35KB), single wave.
// ---------------------------------------------------------------------------
#define ONE2 0x3f8000003f800000ull

// 4 h (dup'ed ek d0..d3) x 1 k x 1 q-pair (eq packs e0..e3, w packs w0..w3)
#define UNITQ(d0, d1, d2, d3, e0, e1, e2, e3, wv0, wv1, wv2, wv3, acc) do {  \
    u64 E1_ = ffma2(d0, e0, ONE2);                                 \
    u64 E2_ = ffma2(d1, e1, ONE2);                                 \
    u64 E3_ = ffma2(d2, e2, ONE2);                                 \
    u64 E4_ = ffma2(d3, e3, ONE2);                                 \
    u64 P12_ = fmul2(E1_, E2_);                                    \
    u64 P34_ = fmul2(E3_, E4_);                                    \
    u64 n12_ = ffma2(wv0, E2_, fmul2(wv1, E1_));                   \
    u64 n34_ = ffma2(wv2, E4_, fmul2(wv3, E3_));                   \
    u64 nt_  = ffma2(n12_, P34_, fmul2(n34_, P12_));               \
    float2 pf_ = unpk(fmul2(P12_, P34_));                          \
    u64 R_ = pk(frcp(pf_.x), frcp(pf_.y));                         \
    acc = ffma2(nt_, R_, acc);                                     \
} while (0)

__global__ __launch_bounds__(256, 4)
void attn_kernel(const float* __restrict__ values,
                 const int*   __restrict__ valid_lens,
                 const float* __restrict__ w_v,
                 float*       __restrict__ out) {
    __shared__ __align__(16) float4 s_eq4[HH];         // [h] -> (q0,q1,q2,q3)
    __shared__ __align__(16) float2 s_w2d[HH];         // dup(-2*w_v[h])
    __shared__ __align__(16) float s_scores[KK * 4];   // exp'ed probs [k][q]
    __shared__ __align__(16) float s_part[8][4][DVV];  // [kgroup][q][v] 16KB
    __shared__ float s_red[8][4];
    __shared__ float s_rden[4];

    int b  = blockIdx.x & 7;                // batch-interleaved blocks
    int q0 = (blockIdx.x >> 3) * 4;
    int tid = threadIdx.x;
    int len = valid_lens[b];

    if (tid < HH) {
        float w = -2.0f * w_v[tid];
        s_w2d[tid] = make_float2(w, w);
    }
    for (int i = tid; i < 4 * HH; i += 256) {
        int qq = i >> 7, h = i & 127;
        ((float*)&s_eq4[h])[qq] = g_Eq[((b * QQ) + q0 + qq) * HH + h];
    }
    __syncthreads();

    float sum0 = 0.f, sum1 = 0.f, sum2 = 0.f, sum3 = 0.f;

    // ---- main loop: scores + exp (k chunks of 512, 2 k per thread) ----
    for (int kbase = 0; kbase < len; kbase += 512) {
        int k0 = kbase + tid * 2;
        if (k0 < len) {
            u64 aP_A = 0ull, aP_B = 0ull;   // q-pair (q0,q1): k0, k0+1
            u64 aQ_A = 0ull, aQ_B = 0ull;   // q-pair (q2,q3): k0, k0+1
            // float4 view: same indices as frozen structure
            const float4* ek4 = (const float4*)g_Ek4 + (size_t)b * (HH/4) * KK + k0;
            float4 p0a = ek4[0];            // hq, k0 (4 h values)
            float4 p0b = ek4[1];            // hq, k0+1
            float4 p1a = ek4[KK];           // hq+1
            float4 p1b = ek4[KK + 1];
#pragma unroll 2
            for (int hq = 0; hq < HH / 4; hq++) {
                float4 ca = p0a, cb = p0b;
                p0a = p1a; p0b = p1b;
                int hn = (hq + 2) & (HH / 4 - 1);     // wrap: harmless reload
                p1a = ek4[(size_t)hn * KK];
                p1b = ek4[(size_t)hn * KK + 1];
                int h = hq * 4;
                // ek dups (shared by both q-pairs)
                u64 dA0 = dup2(ca.x), dA1 = dup2(ca.y);
                u64 dA2 = dup2(ca.z), dA3 = dup2(ca.w);
                u64 dB0 = dup2(cb.x), dB1 = dup2(cb.y);
                u64 dB2 = dup2(cb.z), dB3 = dup2(cb.w);
                // eq q-packs: one LDS.128 per h feeds all 4 q
                float4 e4_0 = s_eq4[h];
                float4 e4_1 = s_eq4[h + 1];
                float4 e4_2 = s_eq4[h + 2];
                float4 e4_3 = s_eq4[h + 3];
                u64 eP0 = ((const u64*)&e4_0)[0], eQ0 = ((const u64*)&e4_0)[1];
                u64 eP1 = ((const u64*)&e4_1)[0], eQ1 = ((const u64*)&e4_1)[1];
                u64 eP2 = ((const u64*)&e4_2)[0], eQ2 = ((const u64*)&e4_2)[1];
                u64 eP3 = ((const u64*)&e4_3)[0], eQ3 = ((const u64*)&e4_3)[1];
                // w dups (LDS.128 x2, shared by both q-pairs)
                float4 w4a = *(const float4*)&s_w2d[h];
                float4 w4b = *(const float4*)&s_w2d[h + 2];
                u64 w0 = ((const u64*)&w4a)[0], w1 = ((const u64*)&w4a)[1];
                u64 w2 = ((const u64*)&w4b)[0], w3 = ((const u64*)&w4b)[1];
                UNITQ(dA0, dA1, dA2, dA3, eP0, eP1, eP2, eP3, w0, w1, w2, w3, aP_A);
                UNITQ(dB0, dB1, dB2, dB3, eP0, eP1, eP2, eP3, w0, w1, w2, w3, aP_B);
                UNITQ(dA0, dA1, dA2, dA3, eQ0, eQ1, eQ2, eQ3, w0, w1, w2, w3, aQ_A);
                UNITQ(dB0, dB1, dB2, dB3, eQ0, eQ1, eQ2, eQ3, w0, w1, w2, w3, aQ_B);
            }
            float2 fPA = unpk(aP_A);        // k0:   (q0, q1)
            float2 fQA = unpk(aQ_A);        // k0:   (q2, q3)
            float2 fPB = unpk(aP_B);        // k0+1: (q0, q1)
            float2 fQB = unpk(aQ_B);        // k0+1: (q2, q3)
            // exp (no max subtraction needed: |score| <= ~18)
            float4 eA = make_float4(fex2(fPA.x * LOG2E), fex2(fPA.y * LOG2E),
                                    fex2(fQA.x * LOG2E), fex2(fQA.y * LOG2E));
            float4 eB = make_float4(fex2(fPB.x * LOG2E), fex2(fPB.y * LOG2E),
                                    fex2(fQB.x * LOG2E), fex2(fQB.y * LOG2E));
            *(float4*)&s_scores[k0 * 4]       = eA;
            *(float4*)&s_scores[(k0 + 1) * 4] = eB;
            sum0 += eA.x; sum1 += eA.y; sum2 += eA.z; sum3 += eA.w;
            if (k0 + 1 < len) {
                sum0 += eB.x; sum1 += eB.y; sum2 += eB.z; sum3 += eB.w;
            }
        }
    }
    // NOTE: if len is odd, s_scores[len] was written but AV reads only k<len.

    // ---- denominator reduction ----
    int warp = tid >> 5, lane = tid & 31;
    for (int o = 16; o > 0; o >>= 1) {
        sum0 += __shfl_xor_sync(0xffffffffu, sum0, o);
        sum1 += __shfl_xor_sync(0xffffffffu, sum1, o);
        sum2 += __shfl_xor_sync(0xffffffffu, sum2, o);
        sum3 += __shfl_xor_sync(0xffffffffu, sum3, o);
    }
    if (lane == 0) {
        s_red[warp][0] = sum0; s_red[warp][1] = sum1;
        s_red[warp][2] = sum2; s_red[warp][3] = sum3;
    }
    __syncthreads();
    if (tid < 4) {
        float s = 0.f;
        for (int w = 0; w < 8; w++) s += s_red[w][tid];
        s_rden[tid] = frcp(s);
    }
    __syncthreads();

    // ---- attn @ V  (8 k-groups x 32 lanes, float4 V loads, f32x2 FMA) ----
    int g = warp;              // k-group = warp (0..7)
    int l = lane;              // v quad index: v0 = 4*l
    u64 a0x = 0ull, a0y = 0ull;   // q0: (v0,v1), (v2,v3)
    u64 a1x = 0ull, a1y = 0ull;   // q1
    u64 a2x = 0ull, a2y = 0ull;   // q2
    u64 a3x = 0ull, a3y = 0ull;   // q3
    const ulonglong2* Vp = (const ulonglong2*)(values + (size_t)b * KK * DVV) + l;
    for (int k = g; k < len; k += 8) {
        float4 p = *(const float4*)&s_scores[k * 4];
        ulonglong2 v = Vp[k * (DVV / 4)];
        u64 p0 = dup2(p.x), p1 = dup2(p.y), p2 = dup2(p.z), p3 = dup2(p.w);
        a0x = ffma2(p0, v.x, a0x); a0y = ffma2(p0, v.y, a0y);
        a1x = ffma2(p1, v.x, a1x); a1y = ffma2(p1, v.y, a1y);
        a2x = ffma2(p2, v.x, a2x); a2y = ffma2(p2, v.y, a2y);
        a3x = ffma2(p3, v.x, a3x); a3y = ffma2(p3, v.y, a3y);
    }
    *(u64*)&s_part[g][0][4 * l]     = a0x;
    *(u64*)&s_part[g][0][4 * l + 2] = a0y;
    *(u64*)&s_part[g][1][4 * l]     = a1x;
    *(u64*)&s_part[g][1][4 * l + 2] = a1y;
    *(u64*)&s_part[g][2][4 * l]     = a2x;
    *(u64*)&s_part[g][2][4 * l + 2] = a2y;
    *(u64*)&s_part[g][3][4 * l]     = a3x;
    *(u64*)&s_part[g][3][4 * l + 2] = a3y;
    __syncthreads();

    // final combine: 512 outputs (4 q x 128 v), 2 per thread
#pragma unroll
    for (int j = 0; j < 2; j++) {
        int idx = tid + j * 256;
        int qq = idx >> 7;
        int v  = idx & 127;
        float rd = s_rden[qq];
        float o = ((s_part[0][qq][v] + s_part[1][qq][v])
                 + (s_part[2][qq][v] + s_part[3][qq][v]))
                + ((s_part[4][qq][v] + s_part[5][qq][v])
                 + (s_part[6][qq][v] + s_part[7][qq][v]));
        out[((size_t)(b * QQ + q0 + qq)) * DVV + v] = o * rd;
    }
}

extern "C" void kernel_launch(void* const* d_in, const int* in_sizes, int n_in,
                              void* d_out, int out_size) {
    const float* queries = (const float*)d_in[0];   // [8,256,256]
    const float* keys    = (const float*)d_in[1];   // [8,1024,256]
    const float* values  = (const float*)d_in[2];   // [8,1024,128]
    const int*   vlens   = (const int*)  d_in[3];   // [8]
    const float* W_q     = (const float*)d_in[4];   // [256,128]
    const float* W_k     = (const float*)d_in[5];   // [256,128]
    const float* w_v     = (const float*)d_in[6];   // [128]
    float* out = (float*)d_out;                     // [8,256,128]

    proj_kernel<<<(BB * QQ + BB * KK) / PR, 512>>>(queries, keys, W_q, W_k);
    attn_kernel<<<BB * (QQ / 4), 256>>>(values, vlens, w_v, out);
}

// round 17
// speedup vs baseline: 1.2416x; 1.2416x over previous
#include <cuda_runtime.h>

#define BB   8
#define QQ   256
#define KK   1024
#define DD   256
#define HH   128
#define DVV  128
#define LOG2E 1.44269504088896340736f

typedef unsigned long long u64;

// Scratch (allocation-free: device globals)
// Ek4 layout: per (b,hq) row of KK float4s; granule of 2 float4s (= 1 k-pair):
//   [h0k0, h0k1, h1k0, h1k1 | h2k0, h2k1, h3k0, h3k1]
// so each aligned u64 lane is an (k0,k1) pack for one h.
__device__ float g_Eq [BB * QQ * HH];        // [b][q][h]   = exp(2*qproj)
__device__ float g_Ek4[BB * (HH/4) * KK * 4];// see layout note above

__device__ __forceinline__ float frcp(float x) {
    float r; asm("rcp.approx.f32 %0, %1;" : "=f"(r) : "f"(x)); return r;
}
__device__ __forceinline__ float fex2(float x) {
    float r; asm("ex2.approx.f32 %0, %1;" : "=f"(r) : "f"(x)); return r;
}
// ---- f32x2 packed helpers (FFMA2: PTX-only, full-rate, IEEE per lane) ----
__device__ __forceinline__ u64 ffma2(u64 a, u64 b, u64 c) {
    u64 d; asm("fma.rn.f32x2 %0, %1, %2, %3;" : "=l"(d) : "l"(a), "l"(b), "l"(c));
    return d;
}
__device__ __forceinline__ u64 fmul2(u64 a, u64 b) {
    u64 d; asm("mul.rn.f32x2 %0, %1, %2;" : "=l"(d) : "l"(a), "l"(b));
    return d;
}
__device__ __forceinline__ u64 dup2(float x) {
    u64 d; asm("mov.b64 %0, {%1, %1};" : "=l"(d) : "f"(x));
    return d;
}
__device__ __forceinline__ float2 unpk(u64 a) {
    float2 f; asm("mov.b64 {%0, %1}, %2;" : "=f"(f.x), "=f"(f.y) : "l"(a));
    return f;
}
__device__ __forceinline__ u64 pk(float x, float y) {
    u64 d; asm("mov.b64 %0, {%1, %2};" : "=l"(d) : "f"(x), "f"(y));
    return d;
}

// ---------------------------------------------------------------------------
// Kernel 1: merged projection + exp (R14 exact). 16 rows per block, 256 thr:
// tid&127 = output column h, tid>>7 = row-half. W native [d][h] (coalesced),
// depth-1 prefetch, f32x2-packed inner loop. K store uses the k-pair layout.
// ---------------------------------------------------------------------------
#define PR 16
__global__ __launch_bounds__(256)
void proj_kernel(const float* __restrict__ Q, const float* __restrict__ Kx,
                 const float* __restrict__ Wq, const float* __restrict__ Wk) {
    __shared__ __align__(16) float xs[PR][DD];     // 16 input rows (16 KB)
    __shared__ float es[HH][PR + 1];               // padded transpose buffer
    int blk  = blockIdx.x;
    bool isK = blk >= (BB * QQ) / PR;              // >= 128
    int rowbase = isK ? (blk - (BB * QQ) / PR) * PR : blk * PR;
    const float* X = isK ? Kx : Q;
    const float* W = isK ? Wk : Wq;
    int tid  = threadIdx.x;
    int h    = tid & 127;                          // output column
    int half = tid >> 7;                           // row-half: 0 or 1
    int r0   = half * 8;                           // first of 8 rows

    {   // coalesced float4 row load (256 threads)
        const float4* Xp = (const float4*)(X + (size_t)rowbase * DD);
        float4* xsp = (float4*)xs;
        for (int i = tid; i < PR * DD / 4; i += 256) xsp[i] = Xp[i];
    }
    __syncthreads();

    u64 acc2[8];
#pragma unroll
    for (int r = 0; r < 8; r++) acc2[r] = 0ull;

    const float* Wp = W + h;
    float w0 = Wp[0 * HH], w1 = Wp[1 * HH], w2 = Wp[2 * HH], w3 = Wp[3 * HH];
    for (int d4 = 0; d4 < DD / 4; d4++) {
        u64 cp01 = pk(w0, w1), cp23 = pk(w2, w3);
        if (d4 + 1 < DD / 4) {                     // prefetch next W quad
            const float* Wn = Wp + (d4 + 1) * 4 * HH;
            w0 = Wn[0 * HH]; w1 = Wn[1 * HH]; w2 = Wn[2 * HH]; w3 = Wn[3 * HH];
        }
        int d = d4 * 4;
#pragma unroll
        for (int r = 0; r < 8; r++) {
            ulonglong2 x2 = *(const ulonglong2*)&xs[r0 + r][d]; // LDS.128
            acc2[r] = ffma2(x2.x, cp01, acc2[r]);
            acc2[r] = ffma2(x2.y, cp23, acc2[r]);
        }
    }

    if (!isK) {
#pragma unroll
        for (int r = 0; r < 8; r++) {
            float2 f = unpk(acc2[r]);
            g_Eq[(rowbase + r0 + r) * HH + h] =
                fex2((f.x + f.y) * (2.0f * LOG2E));
        }
    } else {
#pragma unroll
        for (int r = 0; r < 8; r++) {
            float2 f = unpk(acc2[r]);
            es[h][r0 + r] = fex2((f.x + f.y) * (2.0f * LOG2E));
        }
        __syncthreads();
        int b  = rowbase >> 10;
        int k0 = rowbase & 1023;
        // k-pair interleaved store: float idx within (row,k-pair) granule is
        // h2*2 + (k&1); granule base = (row*KK + k0 + (r&~1)) * 4.
        for (int i = tid; i < HH * PR; i += 256) {
            int hq = i >> 6;              // 64 = PR*4 elements per h-quad
            int r  = (i >> 2) & (PR - 1);
            int h2 = i & 3;
            size_t fi = (((size_t)b * (HH/4) + hq) * KK + k0 + (r & ~1)) * 4
                      + h2 * 2 + (r & 1);
            g_Ek4[fi] = es[hq * 4 + h2][r];
        }
    }
}

// ---------------------------------------------------------------------------
// Kernel 2: fused scores + exp + softmax-denominator + attn@V (R14 base).
// Block = (b, tile of 2 q-rows), 1024 blocks, 256 threads.
//   s = sum_h (-2 w_h) * rcp(1 + Eq*Ek)   (wsum cancels in softmax)
// LOAD ADDRESSES IDENTICAL to the frozen R5 structure. k-pair granule
// layout (zero dup2 in loop), quad-h rcp (4 MUFU/iter).
// SINGLE CHANGE vs R14: hq-loop unroll 2 -> 4 (wider visible window ->
// ptxas can batch up to 8 LDG.128s; MLP_eff 4 -> 8 halves exposed latency).
// ---------------------------------------------------------------------------
#define ONE2 0x3f8000003f800000ull

__global__ __launch_bounds__(256)
void attn_kernel(const float* __restrict__ values,
                 const int*   __restrict__ valid_lens,
                 const float* __restrict__ w_v,
                 float*       __restrict__ out) {
    __shared__ __align__(16) float2 s_eqd[2][HH];      // dup'ed eq, per q
    __shared__ __align__(16) float2 s_w2d[HH];         // dup(-2*w_v[h])
    __shared__ __align__(16) float s_scores[KK * 2];   // exp'ed probs [k][q]
    __shared__ __align__(16) float s_part[8][2][DVV];  // [kgroup][q][v]
    __shared__ float s_red[8][2];
    __shared__ float s_rden[2];

    int b  = blockIdx.x & 7;
    int q0 = (blockIdx.x >> 3) * 2;
    int tid = threadIdx.x;
    int len = valid_lens[b];

    if (tid < HH) {
        float w = -2.0f * w_v[tid];
        s_w2d[tid] = make_float2(w, w);
    }
    if (tid < 2 * HH) {
        int qq = tid >> 7, h = tid & 127;
        float v = g_Eq[((b * QQ) + q0 + qq) * HH + h];
        s_eqd[qq][h] = make_float2(v, v);
    }
    __syncthreads();

    float sum0 = 0.f, sum1 = 0.f;   // denominator partials (q0, q1)

    // ---- main loop: scores + exp (k chunks of 512, 2 k per thread) ----
    for (int kbase = 0; kbase < len; kbase += 512) {
        int k0 = kbase + tid * 2;
        if (k0 < len) {
            u64 accA = 0ull, accB = 0ull;   // (k0,k1) packs for q0 / q1
            // float4 view: same indices as frozen structure
            const float4* ek4 = (const float4*)g_Ek4 + (size_t)b * (HH/4) * KK + k0;
            float4 p0a = ek4[0];            // hq, h0/h1 packs
            float4 p0b = ek4[1];            // hq, h2/h3 packs
            float4 p1a = ek4[KK];           // hq+1
            float4 p1b = ek4[KK + 1];
#pragma unroll 4
            for (int hq = 0; hq < HH / 4; hq++) {
                float4 ca = p0a, cb = p0b;
                p0a = p1a; p0b = p1b;
                int hn = (hq + 2) & (HH / 4 - 1);     // wrap: harmless reload
                p1a = ek4[(size_t)hn * KK];
                p1b = ek4[(size_t)hn * KK + 1];
                int h = hq * 4;
                // ek (k0,k1) packs per h — straight from the loads, no dup
                u64 ek0 = ((const u64*)&ca)[0];
                u64 ek1 = ((const u64*)&ca)[1];
                u64 ek2 = ((const u64*)&cb)[0];
                u64 ek3 = ((const u64*)&cb)[1];
                // w dups (LDS.128 x2)
                float4 w4a = *(const float4*)&s_w2d[h];
                float4 w4b = *(const float4*)&s_w2d[h + 2];
                u64 w0 = ((const u64*)&w4a)[0];
                u64 w1 = ((const u64*)&w4a)[1];
                u64 w2 = ((const u64*)&w4b)[0];
                u64 w3 = ((const u64*)&w4b)[1];
#pragma unroll
                for (int qq = 0; qq < 2; qq++) {
                    // eq dups (LDS.128 x2 per q)
                    float4 e4a = *(const float4*)&s_eqd[qq][h];
                    float4 e4b = *(const float4*)&s_eqd[qq][h + 2];
                    u64 e0 = ((const u64*)&e4a)[0];
                    u64 e1 = ((const u64*)&e4a)[1];
                    u64 e2 = ((const u64*)&e4b)[0];
                    u64 e3 = ((const u64*)&e4b)[1];
                    u64 E1 = ffma2(ek0, e0, ONE2);
                    u64 E2 = ffma2(ek1, e1, ONE2);
                    u64 E3 = ffma2(ek2, e2, ONE2);
                    u64 E4 = ffma2(ek3, e3, ONE2);
                    u64 P12 = fmul2(E1, E2);
                    u64 P34 = fmul2(E3, E4);
                    u64 n12 = ffma2(w0, E2, fmul2(w1, E1));
                    u64 n34 = ffma2(w2, E4, fmul2(w3, E3));
                    u64 nt  = ffma2(n12, P34, fmul2(n34, P12));
                    float2 pf = unpk(fmul2(P12, P34));
                    u64 R = pk(frcp(pf.x), frcp(pf.y));
                    if (qq == 0) accA = ffma2(nt, R, accA);
                    else         accB = ffma2(nt, R, accB);
                }
            }
            float2 f0 = unpk(accA);         // (score k0 q0, score k1 q0)
            float2 f1 = unpk(accB);         // (score k0 q1, score k1 q1)
            // exp (no max subtraction needed: |score| <= ~18)
            float pA0 = fex2(f0.x * LOG2E);
            float pA1 = fex2(f1.x * LOG2E);
            float pB0 = fex2(f0.y * LOG2E);
            float pB1 = fex2(f1.y * LOG2E);
            *(float4*)&s_scores[k0 * 2] = make_float4(pA0, pA1, pB0, pB1);
            bool two = (k0 + 1 < len);
            if (!two) { pB0 = 0.f; pB1 = 0.f; }   // guard odd len tail
            sum0 += pA0 + pB0;
            sum1 += pA1 + pB1;
        }
    }
    // NOTE: if len is odd, s_scores[len] was written but AV reads only k<len.

    // ---- denominator reduction ----
    int warp = tid >> 5, lane = tid & 31;
    for (int o = 16; o > 0; o >>= 1) {
        sum0 += __shfl_xor_sync(0xffffffffu, sum0, o);
        sum1 += __shfl_xor_sync(0xffffffffu, sum1, o);
    }
    if (lane == 0) { s_red[warp][0] = sum0; s_red[warp][1] = sum1; }
    __syncthreads();
    if (tid < 2) {
        float s = 0.f;
        for (int w = 0; w < 8; w++) s += s_red[w][tid];
        s_rden[tid] = frcp(s);
    }
    __syncthreads();

    // ---- attn @ V  (8 k-groups x 32 lanes, float4 V loads, f32x2 FMA) ----
    int g = warp;              // k-group = warp (0..7)
    int l = lane;              // v quad index: v0 = 4*l
    u64 a00 = 0ull, a01 = 0ull;   // q0: (v0,v1), (v2,v3)
    u64 a10 = 0ull, a11 = 0ull;   // q1
    const ulonglong2* Vp = (const ulonglong2*)(values + (size_t)b * KK * DVV) + l;
    for (int k = g; k < len; k += 8) {
        float2 p = *(const float2*)&s_scores[k * 2];
        ulonglong2 v = Vp[k * (DVV / 4)];
        u64 px = dup2(p.x), py = dup2(p.y);
        a00 = ffma2(px, v.x, a00); a01 = ffma2(px, v.y, a01);
        a10 = ffma2(py, v.x, a10); a11 = ffma2(py, v.y, a11);
    }
    *(u64*)&s_part[g][0][4 * l]     = a00;
    *(u64*)&s_part[g][0][4 * l + 2] = a01;
    *(u64*)&s_part[g][1][4 * l]     = a10;
    *(u64*)&s_part[g][1][4 * l + 2] = a11;
    __syncthreads();

    {
        int qq = tid >> 7;
        int v  = tid & 127;
        float rd = s_rden[qq];
        float o = ((s_part[0][qq][v] + s_part[1][qq][v])
                 + (s_part[2][qq][v] + s_part[3][qq][v]))
                + ((s_part[4][qq][v] + s_part[5][qq][v])
                 + (s_part[6][qq][v] + s_part[7][qq][v]));
        out[((size_t)(b * QQ + q0 + qq)) * DVV + v] = o * rd;
    }
}

extern "C" void kernel_launch(void* const* d_in, const int* in_sizes, int n_in,
                              void* d_out, int out_size) {
    const float* queries = (const float*)d_in[0];   // [8,256,256]
    const float* keys    = (const float*)d_in[1];   // [8,1024,256]
    const float* values  = (const float*)d_in[2];   // [8,1024,128]
    const int*   vlens   = (const int*)  d_in[3];   // [8]
    const float* W_q     = (const float*)d_in[4];   // [256,128]
    const float* W_k     = (const float*)d_in[5];   // [256,128]
    const float* w_v     = (const float*)d_in[6];   // [128]
    float* out = (float*)d_out;                     // [8,256,128]

    proj_kernel<<<(BB * QQ + BB * KK) / PR, 256>>>(queries, keys, W_q, W_k);
    attn_kernel<<<BB * (QQ / 2), 256>>>(values, vlens, w_v, out);
}